// round 7
// baseline (speedup 1.0000x reference)
#include <cuda_runtime.h>

#define T_DIM  128
#define C_IN   16
#define H_DIM  64
#define W_DIM  64
#define C_OUT  64

// Conv scratch [T+3, C_OUT, H, W]; +3 zero pad slices so the scan can prefetch
// depth-3 unconditionally. ~137 MB device-global scratch (allowed).
__device__ float g_conv[(size_t)(T_DIM + 3) * C_OUT * H_DIM * W_DIM];
// Transposed weights: [r = ci*9+kh*3+kw][c_out]  (natural c_out float2 pairs)
__device__ float g_wpackT[144 * 64];

// Packed f32x2 FMA (full-rate fp32 on sm_103a; ptxas never auto-emits FFMA2)
#define FMA2(acc, xp, wp) \
    asm("fma.rn.f32x2 %0, %1, %2, %0;" : "+l"(acc) : "l"(xp), "l"(wp))

#define W_FLOATS    (144 * 64)            // 9216 floats  = 36864 B
#define XROW        136                   // duplicated row stride (floats)
#define XS_FLOATS   (16 * 6 * XROW)       // 13056 floats = 52224 B
#define SMEM_BYTES  ((W_FLOATS + XS_FLOATS) * 4)   // 89088 B -> 2 blocks/SM

// One-time weight transpose: OIHW -> [r][c]
__global__ void wpack_kernel(const float* __restrict__ Wt)
{
    int i = blockIdx.x * 256 + threadIdx.x;           // 0..9215
    float w = Wt[i];
    int c = i / 144;
    int r = i - c * 144;
    g_wpackT[r * 64 + c] = w;
}

// Block: 256 thr = 8 warps, covers 4 output rows x 64 cols x 64 c_out for ONE t.
// Warp wg: wr = wg>>2 row-pair (rows 2wr..2wr+1 of the 4), wc = wg&3 owns c_out
// [16wc, 16wc+16) as 8 natural float2 pairs. Lane: rl = lane>>4 row-in-pair,
// cl = lane&15 -> pixels p0=4cl .. p0+3 (P=4).
// x tile stored DUPLICATED in smem: idx 2k,2k+1 hold x[k-1] (66 slots + pad).
// Grid: blockIdx.x = t*16 + rb, rb in [0,16): output rows 4rb..4rb+3.
__global__ void __launch_bounds__(256, 2)
conv3x3_kernel(const float* __restrict__ x,
               const float* __restrict__ bias)
{
    extern __shared__ float smem[];
    float* Ws  = smem;                 // [144][64]
    float* xsd = smem + W_FLOATS;      // [16 ci][6 rows][136]

    const int tid = threadIdx.x;
    const int t   = blockIdx.x >> 4;
    const int rb  = blockIdx.x & 15;

    // ---- weights: conflict-free linear float4 copy from prepacked global ----
    {
        const float4* wp  = (const float4*)g_wpackT;
        float4*       wsm = (float4*)Ws;
#pragma unroll
        for (int k = 0; k < 9; k++)                    // 2304 float4
            wsm[tid + k * 256] = wp[tid + k * 256];
    }

    // ---- x tile: input rows 4rb-1..4rb+4 (6 rows), 16 ci, duplicated {v,v} ----
    // 1536 float4 chunks; thread handles 6: ci = c2/96, rt = (c2%96)/16, w4 = c2%16
#pragma unroll
    for (int k = 0; k < 6; k++) {
        int c2  = tid + k * 256;
        int ci  = c2 / 96;
        int rem = c2 - ci * 96;
        int rt  = rem >> 4;
        int w4  = rem & 15;
        int grow = 4 * rb + rt - 1;
        float4 v = make_float4(0.f, 0.f, 0.f, 0.f);
        if (grow >= 0 && grow < H_DIM)
            v = *(const float4*)(x + (((size_t)t * C_IN + ci) * H_DIM + grow) * W_DIM + 4 * w4);
        float2* d = (float2*)(xsd + (ci * 6 + rt) * XROW + 2 + 8 * w4);
        d[0] = make_float2(v.x, v.x);
        d[1] = make_float2(v.y, v.y);
        d[2] = make_float2(v.z, v.z);
        d[3] = make_float2(v.w, v.w);
    }
    // halo pads: slots k=0 (x[-1]) and k=65 (x[64]) of each of 96 tile rows
    if (tid < 96) {
        float2 z = make_float2(0.f, 0.f);
        *(float2*)(xsd + tid * XROW)       = z;        // idx 0,1
        *(float2*)(xsd + tid * XROW + 130) = z;        // idx 130,131
    }

    const int wg   = tid >> 5;
    const int lane = tid & 31;
    const int wr   = wg >> 2;
    const int wc   = wg & 3;
    const int rl   = lane >> 4;
    const int cl   = lane & 15;
    const int p0   = 4 * cl;               // first pixel col
    const int c0   = wc * 16;              // c_out base (8 pairs)
    const int outrow = 2 * wr + rl;        // local output row 0..3

    // bias pairs
    unsigned long long bp[8];
#pragma unroll
    for (int j = 0; j < 8; j++) {
        float2 bb = *(const float2*)(bias + c0 + 2 * j);
        asm("mov.b64 %0, {%1, %2};" : "=l"(bp[j]) : "f"(bb.x), "f"(bb.y));
    }
    __syncthreads();

    // acc[j][px]: c_out pair j (c0+2j, c0+2j+1), pixel p0+px
    unsigned long long acc[8][4];
#pragma unroll
    for (int j = 0; j < 8; j++) {
        acc[j][0] = bp[j]; acc[j][1] = bp[j];
        acc[j][2] = bp[j]; acc[j][3] = bp[j];
    }

    const float* xwarp = xsd + outrow * XROW + 2 * p0;   // + (ci*6+kh)*XROW
#pragma unroll 1
    for (int ci = 0; ci < C_IN; ci++) {
#pragma unroll
        for (int kh = 0; kh < 3; kh++) {
            // xd[m] = {x[p0+m-1], x[p0+m-1]} for m=0..5 : 3 aligned LDS.128
            const float* xr = xwarp + (ci * 6 + kh) * XROW;
            ulonglong2 x01 = *(const ulonglong2*)xr;
            ulonglong2 x23 = *(const ulonglong2*)(xr + 4);
            ulonglong2 x45 = *(const ulonglong2*)(xr + 8);
            unsigned long long xd[6] = {x01.x, x01.y, x23.x, x23.y, x45.x, x45.y};

            const float* wb = Ws + (ci * 9 + kh * 3) * 64 + c0;
#pragma unroll
            for (int kw = 0; kw < 3; kw++) {
                // 8 c_out pairs, warp-uniform broadcast (4x LDS.128)
                const ulonglong2* wq = (const ulonglong2*)(wb + kw * 64);
                ulonglong2 u0 = wq[0], u1 = wq[1], u2 = wq[2], u3 = wq[3];
                FMA2(acc[0][0], xd[kw+0], u0.x); FMA2(acc[0][1], xd[kw+1], u0.x);
                FMA2(acc[0][2], xd[kw+2], u0.x); FMA2(acc[0][3], xd[kw+3], u0.x);
                FMA2(acc[1][0], xd[kw+0], u0.y); FMA2(acc[1][1], xd[kw+1], u0.y);
                FMA2(acc[1][2], xd[kw+2], u0.y); FMA2(acc[1][3], xd[kw+3], u0.y);
                FMA2(acc[2][0], xd[kw+0], u1.x); FMA2(acc[2][1], xd[kw+1], u1.x);
                FMA2(acc[2][2], xd[kw+2], u1.x); FMA2(acc[2][3], xd[kw+3], u1.x);
                FMA2(acc[3][0], xd[kw+0], u1.y); FMA2(acc[3][1], xd[kw+1], u1.y);
                FMA2(acc[3][2], xd[kw+2], u1.y); FMA2(acc[3][3], xd[kw+3], u1.y);
                FMA2(acc[4][0], xd[kw+0], u2.x); FMA2(acc[4][1], xd[kw+1], u2.x);
                FMA2(acc[4][2], xd[kw+2], u2.x); FMA2(acc[4][3], xd[kw+3], u2.x);
                FMA2(acc[5][0], xd[kw+0], u2.y); FMA2(acc[5][1], xd[kw+1], u2.y);
                FMA2(acc[5][2], xd[kw+2], u2.y); FMA2(acc[5][3], xd[kw+3], u2.y);
                FMA2(acc[6][0], xd[kw+0], u3.x); FMA2(acc[6][1], xd[kw+1], u3.x);
                FMA2(acc[6][2], xd[kw+2], u3.x); FMA2(acc[6][3], xd[kw+3], u3.x);
                FMA2(acc[7][0], xd[kw+0], u3.y); FMA2(acc[7][1], xd[kw+1], u3.y);
                FMA2(acc[7][2], xd[kw+2], u3.y); FMA2(acc[7][3], xd[kw+3], u3.y);
            }
        }
    }

    // ---- epilogue: regroup -> per-c_out float4 stores (coalesced 256B runs) ----
    const int row = 4 * rb + outrow;
    float* op = g_conv + (((size_t)t * C_OUT + c0) * H_DIM + row) * W_DIM + p0;
#pragma unroll
    for (int j = 0; j < 8; j++) {
        float a0, b0, a1, b1, a2, b2, a3, b3;   // aX = c0+2j, bX = c0+2j+1
        asm("mov.b64 {%0,%1}, %2;" : "=f"(a0), "=f"(b0) : "l"(acc[j][0]));
        asm("mov.b64 {%0,%1}, %2;" : "=f"(a1), "=f"(b1) : "l"(acc[j][1]));
        asm("mov.b64 {%0,%1}, %2;" : "=f"(a2), "=f"(b2) : "l"(acc[j][2]));
        asm("mov.b64 {%0,%1}, %2;" : "=f"(a3), "=f"(b3) : "l"(acc[j][3]));
        *(float4*)(op + (size_t)(2 * j)     * H_DIM * W_DIM) = make_float4(a0, a1, a2, a3);
        *(float4*)(op + (size_t)(2 * j + 1) * H_DIM * W_DIM) = make_float4(b0, b1, b2, b3);
    }
}

// LIF scan over T per element. Scalar, 262144 threads, depth-3 prefetch
// (3 zero pad slices make t+3 reads always in-bounds).
__global__ void __launch_bounds__(256)
lif_scan_kernel(float* __restrict__ out)
{
    const int idx = blockIdx.x * 256 + threadIdx.x;        // 0..262143
    const float* __restrict__ cv = (const float*)g_conv;
    const size_t N = 262144;

    float s  = 0.f;
    float c0 = cv[idx];
    float c1 = cv[N + idx];
    float c2 = cv[2 * N + idx];
#pragma unroll 4
    for (int t = 0; t < T_DIM; t++) {
        float cn = cv[(size_t)(t + 3) * N + idx];          // prefetch (pads ok)
        s += c0;
        float sp = (s >= 8.f) ? 1.f : 0.f;
        s = (s >= 8.f) ? 0.f : fmaxf(s, -1.f);
        out[(size_t)t * N + idx] = sp;
        c0 = c1; c1 = c2; c2 = cn;
    }
}

extern "C" void kernel_launch(void* const* d_in, const int* in_sizes, int n_in,
                              void* d_out, int out_size)
{
    const float* x  = (const float*)d_in[0];   // [128,16,64,64]
    const float* Wt = (const float*)d_in[1];   // [64,16,3,3]
    const float* b  = (const float*)d_in[2];   // [64]
    float* out = (float*)d_out;                // [128,64,64,64]

    cudaFuncSetAttribute(conv3x3_kernel,
                         cudaFuncAttributeMaxDynamicSharedMemorySize, SMEM_BYTES);

    wpack_kernel<<<36, 256>>>(Wt);
    conv3x3_kernel<<<T_DIM * 16, 256, SMEM_BYTES>>>(x, b);   // 2048 blocks
    lif_scan_kernel<<<1024, 256>>>(out);
}

// round 8
// speedup vs baseline: 1.2188x; 1.2188x over previous
#include <cuda_runtime.h>

#define T_DIM  128
#define C_IN   16
#define H_DIM  64
#define W_DIM  64
#define C_OUT  64

// Conv scratch [T+3, C_OUT, H, W]; +3 zero pad slices so the scan can prefetch
// depth-3 unconditionally. ~137 MB device-global scratch (allowed).
__device__ float g_conv[(size_t)(T_DIM + 3) * C_OUT * H_DIM * W_DIM];
// Transposed weights: [r = ci*9+kh*3+kw][c_out]  (natural c_out float2 pairs)
__device__ float g_wpackT[144 * 64];

// Packed f32x2 FMA (full-rate fp32 on sm_103a; ptxas never auto-emits FFMA2)
#define FMA2(acc, xp, wp) \
    asm("fma.rn.f32x2 %0, %1, %2, %0;" : "+l"(acc) : "l"(xp), "l"(wp))
#define DUP2(d, v) \
    asm("mov.b64 %0, {%1, %1};" : "=l"(d) : "f"(v))

#define W_FLOATS    (144 * 64)                     // 9216 floats = 36864 B
#define XS_FLOATS   (16 * 4 * 68)                  // 4352 floats = 17408 B
#define SMEM_BYTES  ((W_FLOATS + XS_FLOATS) * 4)   // 54272 B -> 3 blocks/SM

// One-time weight transpose: OIHW -> [r][c]
__global__ void wpack_kernel(const float* __restrict__ Wt)
{
    int i = blockIdx.x * 256 + threadIdx.x;        // 0..9215
    float w = Wt[i];
    int c = i / 144;
    int r = i - c * 144;
    g_wpackT[r * 64 + c] = w;
}

// Block: 256 thr = 8 warps, covers 2 output rows x 64 cols x 64 c_out for ONE t.
// Warp wg owns c_out [8wg, 8wg+8) as 4 natural float2 pairs. Lane: rl = lane>>4
// row-in-pair, cl = lane&15 -> pixels p0=4cl .. p0+3 (P=4).
// x tile [16 ci][4 rows][68]: col i holds x[i-1] (1-float shift, zero halos).
// Grid: blockIdx.x = t*32 + ry; output rows 2ry, 2ry+1.
__global__ void __launch_bounds__(256, 3)
conv3x3_kernel(const float* __restrict__ x,
               const float* __restrict__ bias)
{
    extern __shared__ float smem[];
    float* Ws = smem;                  // [144][64]
    float* xs = smem + W_FLOATS;       // [16][4][68]

    const int tid = threadIdx.x;
    const int t   = blockIdx.x >> 5;
    const int ry  = blockIdx.x & 31;

    // ---- weights: conflict-free linear float4 copy from prepacked global ----
    {
        const float4* wp  = (const float4*)g_wpackT;
        float4*       wsm = (float4*)Ws;
#pragma unroll
        for (int k = 0; k < 9; k++)                // 2304 float4
            wsm[tid + k * 256] = wp[tid + k * 256];
    }

    // ---- x tile: rows 2ry-1..2ry+2, 16 ci, float4 gmem reads, +1 col shift ----
    // 1024 float4 chunks; thread handles 4: ci = i/64, rt = (i%64)/16, w4 = i%16
#pragma unroll
    for (int k = 0; k < 4; k++) {
        int i   = tid + k * 256;
        int ci  = i >> 6;
        int rem = i & 63;
        int rt  = rem >> 4;
        int w4  = rem & 15;
        int grow = 2 * ry + rt - 1;
        float4 v = make_float4(0.f, 0.f, 0.f, 0.f);
        if (grow >= 0 && grow < H_DIM)
            v = *(const float4*)(x + (((size_t)t * C_IN + ci) * H_DIM + grow) * W_DIM + 4 * w4);
        float* d = xs + (ci * 4 + rt) * 68 + 1 + 4 * w4;
        d[0] = v.x; d[1] = v.y; d[2] = v.z; d[3] = v.w;
    }
    // halo pads (cols 0,65,66,67 of each of 64 tile rows)
    if (tid < 64) {
        xs[tid * 68 + 0]  = 0.f;
        xs[tid * 68 + 65] = 0.f;
        xs[tid * 68 + 66] = 0.f;
        xs[tid * 68 + 67] = 0.f;
    }

    const int wg   = tid >> 5;
    const int lane = tid & 31;
    const int rl   = lane >> 4;
    const int cl   = lane & 15;
    const int p0   = 4 * cl;               // first pixel col
    const int c0   = wg * 8;               // c_out base (4 pairs)

    // bias pairs
    unsigned long long bp[4];
#pragma unroll
    for (int j = 0; j < 4; j++) {
        float2 bb = *(const float2*)(bias + c0 + 2 * j);
        asm("mov.b64 %0, {%1, %2};" : "=l"(bp[j]) : "f"(bb.x), "f"(bb.y));
    }
    __syncthreads();

    // acc[j][px]: c_out pair j (c0+2j, c0+2j+1), pixel p0+px
    unsigned long long acc[4][4];
#pragma unroll
    for (int j = 0; j < 4; j++) {
        acc[j][0] = bp[j]; acc[j][1] = bp[j];
        acc[j][2] = bp[j]; acc[j][3] = bp[j];
    }

    const float* xwarp = xs + rl * 68 + p0;          // + (ci*4+kh)*68
#pragma unroll 1
    for (int ci = 0; ci < C_IN; ci++) {
#pragma unroll
        for (int kh = 0; kh < 3; kh++) {
            // x[p0-1 .. p0+4] at smem idx p0..p0+5 : LDS.128 + LDS.64 (aligned)
            const float* xr = xwarp + (ci * 4 + kh) * 68;
            float4 q  = *(const float4*)xr;
            float2 q2 = *(const float2*)(xr + 4);
            unsigned long long xd[6];
            DUP2(xd[0], q.x);  DUP2(xd[1], q.y);  DUP2(xd[2], q.z);
            DUP2(xd[3], q.w);  DUP2(xd[4], q2.x); DUP2(xd[5], q2.y);

            const float* wb = Ws + (ci * 9 + kh * 3) * 64 + c0;
#pragma unroll
            for (int kw = 0; kw < 3; kw++) {
                // 4 c_out pairs, warp-uniform broadcast (2x LDS.128)
                const ulonglong2* wq = (const ulonglong2*)(wb + kw * 64);
                ulonglong2 u0 = wq[0], u1 = wq[1];
                FMA2(acc[0][0], xd[kw+0], u0.x); FMA2(acc[0][1], xd[kw+1], u0.x);
                FMA2(acc[0][2], xd[kw+2], u0.x); FMA2(acc[0][3], xd[kw+3], u0.x);
                FMA2(acc[1][0], xd[kw+0], u0.y); FMA2(acc[1][1], xd[kw+1], u0.y);
                FMA2(acc[1][2], xd[kw+2], u0.y); FMA2(acc[1][3], xd[kw+3], u0.y);
                FMA2(acc[2][0], xd[kw+0], u1.x); FMA2(acc[2][1], xd[kw+1], u1.x);
                FMA2(acc[2][2], xd[kw+2], u1.x); FMA2(acc[2][3], xd[kw+3], u1.x);
                FMA2(acc[3][0], xd[kw+0], u1.y); FMA2(acc[3][1], xd[kw+1], u1.y);
                FMA2(acc[3][2], xd[kw+2], u1.y); FMA2(acc[3][3], xd[kw+3], u1.y);
            }
        }
    }

    // ---- epilogue: regroup -> per-c_out float4 stores (256B warp runs) ----
    const int row = 2 * ry + rl;
    float* op = g_conv + (((size_t)t * C_OUT + c0) * H_DIM + row) * W_DIM + p0;
#pragma unroll
    for (int j = 0; j < 4; j++) {
        float a0, b0, a1, b1, a2, b2, a3, b3;   // aX = c0+2j, bX = c0+2j+1
        asm("mov.b64 {%0,%1}, %2;" : "=f"(a0), "=f"(b0) : "l"(acc[j][0]));
        asm("mov.b64 {%0,%1}, %2;" : "=f"(a1), "=f"(b1) : "l"(acc[j][1]));
        asm("mov.b64 {%0,%1}, %2;" : "=f"(a2), "=f"(b2) : "l"(acc[j][2]));
        asm("mov.b64 {%0,%1}, %2;" : "=f"(a3), "=f"(b3) : "l"(acc[j][3]));
        *(float4*)(op + (size_t)(2 * j)     * H_DIM * W_DIM) = make_float4(a0, a1, a2, a3);
        *(float4*)(op + (size_t)(2 * j + 1) * H_DIM * W_DIM) = make_float4(b0, b1, b2, b3);
    }
}

// LIF scan over T per element. Scalar, 262144 threads, depth-3 prefetch
// (3 zero pad slices make t+3 reads always in-bounds).
__global__ void __launch_bounds__(256)
lif_scan_kernel(float* __restrict__ out)
{
    const int idx = blockIdx.x * 256 + threadIdx.x;        // 0..262143
    const float* __restrict__ cv = (const float*)g_conv;
    const size_t N = 262144;

    float s  = 0.f;
    float c0 = cv[idx];
    float c1 = cv[N + idx];
    float c2 = cv[2 * N + idx];
#pragma unroll 4
    for (int t = 0; t < T_DIM; t++) {
        float cn = cv[(size_t)(t + 3) * N + idx];          // prefetch (pads ok)
        s += c0;
        float sp = (s >= 8.f) ? 1.f : 0.f;
        s = (s >= 8.f) ? 0.f : fmaxf(s, -1.f);
        out[(size_t)t * N + idx] = sp;
        c0 = c1; c1 = c2; c2 = cn;
    }
}

extern "C" void kernel_launch(void* const* d_in, const int* in_sizes, int n_in,
                              void* d_out, int out_size)
{
    const float* x  = (const float*)d_in[0];   // [128,16,64,64]
    const float* Wt = (const float*)d_in[1];   // [64,16,3,3]
    const float* b  = (const float*)d_in[2];   // [64]
    float* out = (float*)d_out;                // [128,64,64,64]

    cudaFuncSetAttribute(conv3x3_kernel,
                         cudaFuncAttributeMaxDynamicSharedMemorySize, SMEM_BYTES);

    wpack_kernel<<<36, 256>>>(Wt);
    conv3x3_kernel<<<T_DIM * 32, 256, SMEM_BYTES>>>(x, b);   // 4096 blocks
    lif_scan_kernel<<<1024, 256>>>(out);
}